// round 2
// baseline (speedup 1.0000x reference)
#include <cuda_runtime.h>
#include <cuda_bf16.h>

#define OUT_DIM 11008
#define IN_DIM  4096
#define MTOK    2048

// ---------------- scratch (device globals; no runtime allocation) ----------------
__device__ float          g_W  [(size_t)OUT_DIM * IN_DIM];
__device__ __nv_bfloat16  g_Whi[(size_t)OUT_DIM * IN_DIM];
__device__ __nv_bfloat16  g_Wlo[(size_t)OUT_DIM * IN_DIM];
__device__ __nv_bfloat16  g_Xhi[(size_t)MTOK * IN_DIM];
__device__ __nv_bfloat16  g_Xlo[(size_t)MTOK * IN_DIM];

static __device__ __forceinline__ unsigned smem_u32(const void* p) {
    return (unsigned)__cvta_generic_to_shared(p);
}

#define CP16(dst_u32, src_ptr) \
    asm volatile("cp.async.cg.shared.global [%0], [%1], 16;" \
                 :: "r"(dst_u32), "l"(src_ptr) : "memory")

#define LDSM4(R, ADDR) \
    asm volatile("ldmatrix.sync.aligned.m8n8.x4.shared.b16 {%0,%1,%2,%3}, [%4];" \
                 : "=r"((R)[0]), "=r"((R)[1]), "=r"((R)[2]), "=r"((R)[3]) : "r"(ADDR))

#define MMA16816(C, A, B0, B1) \
    asm volatile("mma.sync.aligned.m16n8k16.row.col.f32.bf16.bf16.f32 " \
                 "{%0,%1,%2,%3}, {%4,%5,%6,%7}, {%8,%9}, {%0,%1,%2,%3};" \
                 : "+f"((C)[0]), "+f"((C)[1]), "+f"((C)[2]), "+f"((C)[3]) \
                 : "r"((A)[0]), "r"((A)[1]), "r"((A)[2]), "r"((A)[3]), \
                   "r"(B0), "r"(B1))

// ---------------- kernel 1: dequant packed int4 -> fp32 W ----------------
__global__ void dequant_kernel(const int* __restrict__ packed,
                               const float* __restrict__ scales) {
    size_t i = (size_t)blockIdx.x * blockDim.x + threadIdx.x;
    const size_t n = (size_t)OUT_DIM * (IN_DIM / 2);
    if (i >= n) return;
    int v = packed[i];
    int row = (int)(i >> 11);               // IN_DIM/2 = 2048
    float s = scales[row];
    float2 w;
    w.x = (float)((v & 15) - 8) * s;        // original column 2j
    w.y = (float)(((v >> 4) & 15) - 8) * s; // original column 2j+1
    reinterpret_cast<float2*>(g_W)[i] = w;
}

// ---------------- kernel 2: sparse scatter-add ----------------
__global__ void scatter_kernel(const float* __restrict__ vals,
                               const int* __restrict__ rows,
                               const int* __restrict__ cols, int nnz) {
    int i = blockIdx.x * blockDim.x + threadIdx.x;
    if (i >= nnz) return;
    atomicAdd(&g_W[(size_t)rows[i] * IN_DIM + cols[i]], vals[i]);
}

// ---------------- kernel 3: split W -> (hi, lo) bf16 ----------------
__global__ void split_w_kernel() {
    size_t i = (size_t)blockIdx.x * blockDim.x + threadIdx.x;
    const size_t n4 = (size_t)OUT_DIM * IN_DIM / 4;
    if (i >= n4) return;
    float4 w = reinterpret_cast<const float4*>(g_W)[i];
    __nv_bfloat16 h0 = __float2bfloat16(w.x);
    __nv_bfloat16 h1 = __float2bfloat16(w.y);
    __nv_bfloat16 h2 = __float2bfloat16(w.z);
    __nv_bfloat16 h3 = __float2bfloat16(w.w);
    __nv_bfloat16 l0 = __float2bfloat16(w.x - __bfloat162float(h0));
    __nv_bfloat16 l1 = __float2bfloat16(w.y - __bfloat162float(h1));
    __nv_bfloat16 l2 = __float2bfloat16(w.z - __bfloat162float(h2));
    __nv_bfloat16 l3 = __float2bfloat16(w.w - __bfloat162float(h3));
    __nv_bfloat162* hi2 = reinterpret_cast<__nv_bfloat162*>(g_Whi) + 2 * i;
    __nv_bfloat162* lo2 = reinterpret_cast<__nv_bfloat162*>(g_Wlo) + 2 * i;
    hi2[0] = __halves2bfloat162(h0, h1);
    hi2[1] = __halves2bfloat162(h2, h3);
    lo2[0] = __halves2bfloat162(l0, l1);
    lo2[1] = __halves2bfloat162(l2, l3);
}

// ---------------- kernel 4: split x -> (hi, lo) bf16 ----------------
__global__ void split_x_kernel(const float* __restrict__ x) {
    size_t i = (size_t)blockIdx.x * blockDim.x + threadIdx.x;
    const size_t n4 = (size_t)MTOK * IN_DIM / 4;
    if (i >= n4) return;
    float4 w = reinterpret_cast<const float4*>(x)[i];
    __nv_bfloat16 h0 = __float2bfloat16(w.x);
    __nv_bfloat16 h1 = __float2bfloat16(w.y);
    __nv_bfloat16 h2 = __float2bfloat16(w.z);
    __nv_bfloat16 h3 = __float2bfloat16(w.w);
    __nv_bfloat16 l0 = __float2bfloat16(w.x - __bfloat162float(h0));
    __nv_bfloat16 l1 = __float2bfloat16(w.y - __bfloat162float(h1));
    __nv_bfloat16 l2 = __float2bfloat16(w.z - __bfloat162float(h2));
    __nv_bfloat16 l3 = __float2bfloat16(w.w - __bfloat162float(h3));
    __nv_bfloat162* hi2 = reinterpret_cast<__nv_bfloat162*>(g_Xhi) + 2 * i;
    __nv_bfloat162* lo2 = reinterpret_cast<__nv_bfloat162*>(g_Xlo) + 2 * i;
    hi2[0] = __halves2bfloat162(h0, h1);
    hi2[1] = __halves2bfloat162(h2, h3);
    lo2[0] = __halves2bfloat162(l0, l1);
    lo2[1] = __halves2bfloat162(l2, l3);
}

// ---------------- kernel 5: mma.sync bf16 split GEMM ----------------
// acc = Xhi*Whi^T + Xlo*Whi^T + Xhi*Wlo^T, accumulated in registers over all
// 3 segments. CTA tile 128x128, K-tile 32, 3-stage cp.async pipeline.
// smem tile layout (A and B identical): row r (0..127), 16B chunk c (0..3):
//   offset = r*64 + ((c ^ ((r>>1)&3)) << 4)   -- conflict-free STS.128 + LDSM
#define KTILE 32
#define STAGE_BYTES 16384
#define N_ITERS (3 * IN_DIM / KTILE)   // 384

__global__ void __launch_bounds__(256, 2) gemm_kernel(float* __restrict__ out) {
    extern __shared__ char smem[];
    const int tid  = threadIdx.x;
    const int lane = tid & 31;
    const int w    = tid >> 5;
    const int wm   = w & 1;        // 0..1 : 64-row half
    const int wn   = w >> 1;       // 0..3 : 32-col quarter
    const int mt   = blockIdx.x;   // 0..15
    const int nt   = blockIdx.y;   // 0..85

    const __nv_bfloat16* Aseg[3] = { g_Xhi, g_Xlo, g_Xhi };
    const __nv_bfloat16* Bseg[3] = { g_Whi, g_Whi, g_Wlo };

    float c[4][4][4];
    #pragma unroll
    for (int mi = 0; mi < 4; ++mi)
        #pragma unroll
        for (int ni = 0; ni < 4; ++ni)
            #pragma unroll
            for (int q = 0; q < 4; ++q) c[mi][ni][q] = 0.f;

    // per-thread cp.async mapping: 512 16B-chunks/tile; each thread does 2 per operand
    const int lr0 = tid >> 2;            // rows 0..63
    const int lr1 = lr0 + 64;            // rows 64..127
    const int lc  = tid & 3;             // chunk 0..3
    const int dO0 = lr0 * 64 + (((lc ^ ((lr0 >> 1) & 3))) << 4);
    const int dO1 = lr1 * 64 + (((lc ^ ((lr1 >> 1) & 3))) << 4);
    const unsigned sbase = smem_u32(smem);

    // ---- pipeline ----
    #define LOAD_TILE(it_) do {                                                   \
        int seg_ = (it_) >> 7;                                                    \
        int k0_  = ((it_) & 127) << 5;                                            \
        const __nv_bfloat16* Ab_ = Aseg[seg_] + (size_t)mt * 128 * IN_DIM + k0_;  \
        const __nv_bfloat16* Bb_ = Bseg[seg_] + (size_t)nt * 128 * IN_DIM + k0_;  \
        unsigned sa_ = sbase + ((it_) % 3) * STAGE_BYTES;                         \
        unsigned sb_ = sa_ + 8192;                                                \
        CP16(sa_ + dO0, Ab_ + (size_t)lr0 * IN_DIM + lc * 8);                     \
        CP16(sa_ + dO1, Ab_ + (size_t)lr1 * IN_DIM + lc * 8);                     \
        CP16(sb_ + dO0, Bb_ + (size_t)lr0 * IN_DIM + lc * 8);                     \
        CP16(sb_ + dO1, Bb_ + (size_t)lr1 * IN_DIM + lc * 8);                     \
    } while (0)

    LOAD_TILE(0);
    asm volatile("cp.async.commit_group;" ::: "memory");
    LOAD_TILE(1);
    asm volatile("cp.async.commit_group;" ::: "memory");

    for (int it = 0; it < N_ITERS; ++it) {
        if (it + 2 < N_ITERS) LOAD_TILE(it + 2);
        asm volatile("cp.async.commit_group;" ::: "memory");
        asm volatile("cp.async.wait_group 2;" ::: "memory");
        __syncthreads();

        unsigned sa = sbase + (it % 3) * STAGE_BYTES;
        unsigned sb = sa + 8192;
        #pragma unroll
        for (int kk = 0; kk < 2; ++kk) {
            unsigned a[4][4];
            #pragma unroll
            for (int mi = 0; mi < 4; ++mi) {
                int r = wm * 64 + mi * 16 + (lane & 15);
                int ci = kk * 2 + (lane >> 4);
                unsigned addr = sa + r * 64 + (((ci ^ ((r >> 1) & 3))) << 4);
                LDSM4(a[mi], addr);
            }
            unsigned b[2][4];
            #pragma unroll
            for (int nj = 0; nj < 2; ++nj) {
                int r = wn * 32 + nj * 16 + (lane & 7) + ((lane >> 4) << 3);
                int ci = kk * 2 + ((lane >> 3) & 1);
                unsigned addr = sb + r * 64 + (((ci ^ ((r >> 1) & 3))) << 4);
                LDSM4(b[nj], addr);
            }
            #pragma unroll
            for (int mi = 0; mi < 4; ++mi)
                #pragma unroll
                for (int ni = 0; ni < 4; ++ni)
                    MMA16816(c[mi][ni], a[mi],
                             b[ni >> 1][(ni & 1) * 2 + 0],
                             b[ni >> 1][(ni & 1) * 2 + 1]);
        }
        __syncthreads();
    }

    // ---- epilogue: direct fp32 stores ----
    const int r0 = mt * 128 + wm * 64 + (lane >> 2);
    const int c0 = nt * 128 + wn * 32 + (lane & 3) * 2;
    #pragma unroll
    for (int mi = 0; mi < 4; ++mi) {
        #pragma unroll
        for (int ni = 0; ni < 4; ++ni) {
            size_t rowA = (size_t)(r0 + mi * 16) * OUT_DIM + c0 + ni * 8;
            size_t rowB = rowA + (size_t)8 * OUT_DIM;
            float2 v01; v01.x = c[mi][ni][0]; v01.y = c[mi][ni][1];
            float2 v23; v23.x = c[mi][ni][2]; v23.y = c[mi][ni][3];
            *reinterpret_cast<float2*>(out + rowA) = v01;
            *reinterpret_cast<float2*>(out + rowB) = v23;
        }
    }
}

// ---------------- launcher ----------------
extern "C" void kernel_launch(void* const* d_in, const int* in_sizes, int n_in,
                              void* d_out, int out_size) {
    const float* x      = (const float*)d_in[0];
    const float* scales = (const float*)d_in[1];
    const float* vals   = (const float*)d_in[2];
    const int*   packed = (const int*)d_in[3];
    const int*   rows   = (const int*)d_in[4];
    const int*   cols   = (const int*)d_in[5];
    float* out = (float*)d_out;
    int nnz = in_sizes[2];

    {
        size_t n = (size_t)OUT_DIM * (IN_DIM / 2);
        dequant_kernel<<<(unsigned)((n + 255) / 256), 256>>>(packed, scales);
    }
    scatter_kernel<<<(nnz + 255) / 256, 256>>>(vals, rows, cols, nnz);
    {
        size_t n4 = (size_t)OUT_DIM * IN_DIM / 4;
        split_w_kernel<<<(unsigned)((n4 + 255) / 256), 256>>>();
    }
    {
        size_t n4 = (size_t)MTOK * IN_DIM / 4;
        split_x_kernel<<<(unsigned)((n4 + 255) / 256), 256>>>(x);
    }
    {
        dim3 grid(MTOK / 128, OUT_DIM / 128);  // x fastest -> 16 CTAs share a W n-tile in L2
        gemm_kernel<<<grid, 256, 3 * STAGE_BYTES>>>(out);
    }
}

// round 3
// speedup vs baseline: 2.6968x; 2.6968x over previous
#include <cuda_runtime.h>
#include <cuda_fp16.h>

#define OUT_DIM 11008
#define IN_DIM  4096
#define MTOK    2048

// ---------------- scratch (device globals; no runtime allocation) ----------------
__device__ __half g_Wh[(size_t)OUT_DIM * IN_DIM];
__device__ __half g_Xh[(size_t)MTOK * IN_DIM];

static __device__ __forceinline__ unsigned smem_u32(const void* p) {
    return (unsigned)__cvta_generic_to_shared(p);
}

#define CP16(dst_u32, src_ptr) \
    asm volatile("cp.async.cg.shared.global [%0], [%1], 16;" \
                 :: "r"(dst_u32), "l"(src_ptr) : "memory")

#define LDSM4(R, ADDR) \
    asm volatile("ldmatrix.sync.aligned.m8n8.x4.shared.b16 {%0,%1,%2,%3}, [%4];" \
                 : "=r"((R)[0]), "=r"((R)[1]), "=r"((R)[2]), "=r"((R)[3]) : "r"(ADDR))

#define MMA16816(C, A, B0, B1) \
    asm volatile("mma.sync.aligned.m16n8k16.row.col.f32.f16.f16.f32 " \
                 "{%0,%1,%2,%3}, {%4,%5,%6,%7}, {%8,%9}, {%0,%1,%2,%3};" \
                 : "+f"((C)[0]), "+f"((C)[1]), "+f"((C)[2]), "+f"((C)[3]) \
                 : "r"((A)[0]), "r"((A)[1]), "r"((A)[2]), "r"((A)[3]), \
                   "r"(B0), "r"(B1))

// ---------------- kernel 1: dequant packed int4 -> fp16 W ----------------
__global__ void dequant_kernel(const int* __restrict__ packed,
                               const float* __restrict__ scales) {
    size_t i = (size_t)blockIdx.x * blockDim.x + threadIdx.x;
    const size_t n = (size_t)OUT_DIM * (IN_DIM / 2);
    if (i >= n) return;
    int v = packed[i];
    int row = (int)(i >> 11);               // IN_DIM/2 = 2048
    float s = scales[row];
    float lo = (float)((v & 15) - 8) * s;         // original column 2j
    float hi = (float)(((v >> 4) & 15) - 8) * s;  // original column 2j+1
    reinterpret_cast<__half2*>(g_Wh)[i] = __floats2half2_rn(lo, hi);
}

// ---------------- kernel 2: sparse scatter-add (native fp16 atomics) ----------------
__global__ void scatter_kernel(const float* __restrict__ vals,
                               const int* __restrict__ rows,
                               const int* __restrict__ cols, int nnz) {
    int i = blockIdx.x * blockDim.x + threadIdx.x;
    if (i >= nnz) return;
    atomicAdd(&g_Wh[(size_t)rows[i] * IN_DIM + cols[i]], __float2half(vals[i]));
}

// ---------------- kernel 3: convert x -> fp16 ----------------
__global__ void convert_x_kernel(const float* __restrict__ x) {
    size_t i = (size_t)blockIdx.x * blockDim.x + threadIdx.x;
    const size_t n4 = (size_t)MTOK * IN_DIM / 4;
    if (i >= n4) return;
    float4 v = reinterpret_cast<const float4*>(x)[i];
    __half2* o = reinterpret_cast<__half2*>(g_Xh) + 2 * i;
    o[0] = __floats2half2_rn(v.x, v.y);
    o[1] = __floats2half2_rn(v.z, v.w);
}

// ---------------- kernel 4: mma.sync fp16 GEMM ----------------
// out = Xh * Wh^T, fp32 accumulate. CTA tile 128x128, K-tile 32, 3-stage cp.async.
// smem tile layout (A and B identical): row r (0..127), 16B chunk c (0..3):
//   offset = r*64 + ((c ^ ((r>>1)&3)) << 4)   -- conflict-free STS.128 + LDSM
#define KTILE 32
#define STAGE_BYTES 16384
#define N_ITERS (IN_DIM / KTILE)   // 128

__global__ void __launch_bounds__(256, 2) gemm_kernel(float* __restrict__ out) {
    extern __shared__ char smem[];
    const int tid  = threadIdx.x;
    const int lane = tid & 31;
    const int w    = tid >> 5;
    const int wm   = w & 1;        // 0..1 : 64-row half
    const int wn   = w >> 1;       // 0..3 : 32-col quarter
    const int mt   = blockIdx.x;   // 0..15
    const int nt   = blockIdx.y;   // 0..85

    float c[4][4][4];
    #pragma unroll
    for (int mi = 0; mi < 4; ++mi)
        #pragma unroll
        for (int ni = 0; ni < 4; ++ni)
            #pragma unroll
            for (int q = 0; q < 4; ++q) c[mi][ni][q] = 0.f;

    // per-thread cp.async mapping: 512 16B-chunks/tile; each thread does 2 per operand
    const int lr0 = tid >> 2;            // rows 0..63
    const int lr1 = lr0 + 64;            // rows 64..127
    const int lc  = tid & 3;             // chunk 0..3
    const int dO0 = lr0 * 64 + (((lc ^ ((lr0 >> 1) & 3))) << 4);
    const int dO1 = lr1 * 64 + (((lc ^ ((lr1 >> 1) & 3))) << 4);
    const unsigned sbase = smem_u32(smem);

    const __half* Ab = g_Xh + (size_t)mt * 128 * IN_DIM;
    const __half* Bb = g_Wh + (size_t)nt * 128 * IN_DIM;

    #define LOAD_TILE(it_) do {                                                   \
        int k0_ = (it_) << 5;                                                     \
        unsigned sa_ = sbase + ((it_) % 3) * STAGE_BYTES;                         \
        unsigned sb_ = sa_ + 8192;                                                \
        CP16(sa_ + dO0, Ab + (size_t)lr0 * IN_DIM + k0_ + lc * 8);                \
        CP16(sa_ + dO1, Ab + (size_t)lr1 * IN_DIM + k0_ + lc * 8);                \
        CP16(sb_ + dO0, Bb + (size_t)lr0 * IN_DIM + k0_ + lc * 8);                \
        CP16(sb_ + dO1, Bb + (size_t)lr1 * IN_DIM + k0_ + lc * 8);                \
    } while (0)

    LOAD_TILE(0);
    asm volatile("cp.async.commit_group;" ::: "memory");
    LOAD_TILE(1);
    asm volatile("cp.async.commit_group;" ::: "memory");

    for (int it = 0; it < N_ITERS; ++it) {
        if (it + 2 < N_ITERS) LOAD_TILE(it + 2);
        asm volatile("cp.async.commit_group;" ::: "memory");
        asm volatile("cp.async.wait_group 2;" ::: "memory");
        __syncthreads();

        unsigned sa = sbase + (it % 3) * STAGE_BYTES;
        unsigned sb = sa + 8192;
        #pragma unroll
        for (int kk = 0; kk < 2; ++kk) {
            unsigned a[4][4];
            #pragma unroll
            for (int mi = 0; mi < 4; ++mi) {
                int r = wm * 64 + mi * 16 + (lane & 15);
                int ci = kk * 2 + (lane >> 4);
                unsigned addr = sa + r * 64 + (((ci ^ ((r >> 1) & 3))) << 4);
                LDSM4(a[mi], addr);
            }
            unsigned b[2][4];
            #pragma unroll
            for (int nj = 0; nj < 2; ++nj) {
                int r = wn * 32 + nj * 16 + (lane & 7) + ((lane >> 4) << 3);
                int ci = kk * 2 + ((lane >> 3) & 1);
                unsigned addr = sb + r * 64 + (((ci ^ ((r >> 1) & 3))) << 4);
                LDSM4(b[nj], addr);
            }
            #pragma unroll
            for (int mi = 0; mi < 4; ++mi)
                #pragma unroll
                for (int ni = 0; ni < 4; ++ni)
                    MMA16816(c[mi][ni], a[mi],
                             b[ni >> 1][(ni & 1) * 2 + 0],
                             b[ni >> 1][(ni & 1) * 2 + 1]);
        }
        __syncthreads();
    }

    // ---- epilogue: direct fp32 stores ----
    const int r0 = mt * 128 + wm * 64 + (lane >> 2);
    const int c0 = nt * 128 + wn * 32 + (lane & 3) * 2;
    #pragma unroll
    for (int mi = 0; mi < 4; ++mi) {
        #pragma unroll
        for (int ni = 0; ni < 4; ++ni) {
            size_t rowA = (size_t)(r0 + mi * 16) * OUT_DIM + c0 + ni * 8;
            size_t rowB = rowA + (size_t)8 * OUT_DIM;
            float2 v01; v01.x = c[mi][ni][0]; v01.y = c[mi][ni][1];
            float2 v23; v23.x = c[mi][ni][2]; v23.y = c[mi][ni][3];
            *reinterpret_cast<float2*>(out + rowA) = v01;
            *reinterpret_cast<float2*>(out + rowB) = v23;
        }
    }
}

// ---------------- launcher ----------------
extern "C" void kernel_launch(void* const* d_in, const int* in_sizes, int n_in,
                              void* d_out, int out_size) {
    const float* x      = (const float*)d_in[0];
    const float* scales = (const float*)d_in[1];
    const float* vals   = (const float*)d_in[2];
    const int*   packed = (const int*)d_in[3];
    const int*   rows   = (const int*)d_in[4];
    const int*   cols   = (const int*)d_in[5];
    float* out = (float*)d_out;
    int nnz = in_sizes[2];

    {
        size_t n = (size_t)OUT_DIM * (IN_DIM / 2);
        dequant_kernel<<<(unsigned)((n + 255) / 256), 256>>>(packed, scales);
    }
    scatter_kernel<<<(nnz + 255) / 256, 256>>>(vals, rows, cols, nnz);
    {
        size_t n4 = (size_t)MTOK * IN_DIM / 4;
        convert_x_kernel<<<(unsigned)((n4 + 255) / 256), 256>>>(x);
    }
    {
        dim3 grid(MTOK / 128, OUT_DIM / 128);  // x fastest -> 16 CTAs share a W n-tile in L2
        gemm_kernel<<<grid, 256, 3 * STAGE_BYTES>>>(out);
    }
}